// round 5
// baseline (speedup 1.0000x reference)
#include <cuda_runtime.h>
#include <stdint.h>

#define NOPP 3
#define NS   80
#define NA   6
#define DD   512
#define RK1  8     // batch rows per k1 block
#define RK2  16    // batch rows per k2 block
#define SCHUNK 16  // samples per k2 block (NS/SCHUNK = 5 blocks per row)

// ---------------- device scratch ----------------
__device__ float g_einv[NOPP * 4096 * NA];
__device__ float g_dist[NOPP * 4096 * NA];
__device__ float g_base[4096 * NA];
__device__ unsigned long long g_acc[4096][8];   // fixed-point num[0..5], den[6]
__device__ unsigned int g_tick[4096 / RK2];
__device__ unsigned long long g_entacc;
__device__ unsigned int g_entticket;

#define FPSCALE 1.099511627776e12   // 2^40

// ---------------- threefry2x32, key=(0,42), counter=(0,i); out = x0^x1 ----------------
__device__ __forceinline__ uint32_t tf_fold(uint32_t c1)
{
    const uint32_t KS1 = 42u;
    const uint32_t KS2 = 0x1BD11BDAu ^ 42u;   // ks0 = 0
    uint32_t x0 = 0u, x1 = c1 + KS1;
#define TFR(r) { x0 += x1; x1 = __funnelshift_l(x1, x1, (r)); x1 ^= x0; }
    TFR(13) TFR(15) TFR(26) TFR(6)
    x0 += KS1; x1 += KS2 + 1u;
    TFR(17) TFR(29) TFR(16) TFR(24)
    x0 += KS2; x1 += 2u;
    TFR(13) TFR(15) TFR(26) TFR(6)
    x1 += KS1 + 3u;
    TFR(17) TFR(29) TFR(16) TFR(24)
    x0 += KS1; x1 += KS2 + 4u;
    TFR(13) TFR(15) TFR(26) TFR(6)
    x0 += KS2; x1 += 5u;
#undef TFR
    return x0 ^ x1;
}

__device__ __forceinline__ float bits_to_t_fast(uint32_t bits)
{
    float f = __uint_as_float((bits >> 9) | 0x3f800000u) - 1.0f;
    return -__logf(f + 1.17549435e-38f);
}

// ---------------- k1: GEMM + softmax/einv/dist/base + entropy ----------------
__global__ void __launch_bounds__(256) k1(
    const float* __restrict__ x, const float* __restrict__ Wopp,
    const float* __restrict__ bopp, const float* __restrict__ W,
    const float* __restrict__ bias, float* __restrict__ out,
    int B, int out_size)
{
    __shared__ float xs[RK1 * DD];           // 16 KB
    __shared__ float vals[RK1][25];
    __shared__ float entkb[RK1 * 3];

    int tid  = threadIdx.x;
    int warp = tid >> 5;
    int lane = tid & 31;
    int b0   = blockIdx.x * RK1;

    if (b0 + RK1 <= B) {
        const float4* x4 = reinterpret_cast<const float4*>(x + (size_t)b0 * DD);
        float4* xs4 = reinterpret_cast<float4*>(xs);
        for (int i = tid; i < RK1 * DD / 4; i += 256) xs4[i] = x4[i];
    } else {
        for (int i = tid; i < RK1 * DD; i += 256) {
            int r = i / DD;
            xs[i] = (b0 + r < B) ? x[(size_t)(b0 + r) * DD + (i % DD)] : 0.0f;
        }
    }

    // per-warp columns 3w..3w+2 in registers
    float w0[16], w1[16], w2[16];
    {
        int c = 3 * warp;
        const float* s0 = (c + 0 < 18) ? (Wopp + (size_t)((c + 0) / 6) * DD * NA + ((c + 0) % 6))
                                       : (W + (c + 0 - 18));
        const float* s1 = (c + 1 < 18) ? (Wopp + (size_t)((c + 1) / 6) * DD * NA + ((c + 1) % 6))
                                       : (W + (c + 1 - 18));
        const float* s2 = (c + 2 < 18) ? (Wopp + (size_t)((c + 2) / 6) * DD * NA + ((c + 2) % 6))
                                       : (W + (c + 2 - 18));
#pragma unroll
        for (int j = 0; j < 16; j++) {
            size_t idx = (size_t)(lane + 32 * j) * NA;
            w0[j] = s0[idx]; w1[j] = s1[idx]; w2[j] = s2[idx];
        }
    }
    __syncthreads();

    for (int r = 0; r < RK1; r++) {
        const float* xr = xs + r * DD + lane;
        float a0 = 0.f, a1 = 0.f, a2 = 0.f;
#pragma unroll
        for (int j = 0; j < 16; j++) {
            float xv = xr[32 * j];
            a0 = fmaf(xv, w0[j], a0);
            a1 = fmaf(xv, w1[j], a1);
            a2 = fmaf(xv, w2[j], a2);
        }
#pragma unroll
        for (int off = 16; off; off >>= 1) {
            a0 += __shfl_down_sync(0xffffffffu, a0, off);
            a1 += __shfl_down_sync(0xffffffffu, a1, off);
            a2 += __shfl_down_sync(0xffffffffu, a2, off);
        }
        if (lane == 0) {
            vals[r][3 * warp + 0] = a0;
            vals[r][3 * warp + 1] = a1;
            vals[r][3 * warp + 2] = a2;
        }
    }
    __syncthreads();

    if (tid < RK1 * 3) {
        int r = tid / 3, k = tid % 3, b = b0 + r;
        if (b < B) {
            float l[NA], m = -1e30f;
#pragma unroll
            for (int a = 0; a < NA; a++) {
                l[a] = vals[r][k * 6 + a] + bopp[k * 6 + a];
                m = fmaxf(m, l[a]);
            }
            float e[NA], S = 0.0f;
#pragma unroll
            for (int a = 0; a < NA; a++) { e[a] = expf(l[a] - m); S += e[a]; }
            float logS = logf(S);
            float ent = 0.0f;
            size_t go = ((size_t)k * B + b) * NA;
            size_t distoff = (size_t)B * NA + go;
#pragma unroll
            for (int a = 0; a < NA; a++) {
                float d = e[a] / S;
                g_dist[go + a] = d;
                g_einv[go + a] = expf(-l[a]);
                ent -= d * ((l[a] - m) - logS);
                if (out_size >= B * 24) out[distoff + a] = d;
            }
            entkb[tid] = ent;
        } else entkb[tid] = 0.0f;
    } else if (tid < RK1 * 3 + RK1 * 6) {
        int t2 = tid - RK1 * 3;
        int r = t2 / 6, a = t2 % 6, b = b0 + r;
        if (b < B) g_base[b * NA + a] = vals[r][18 + a] + bias[a];
    }
    __syncthreads();

    // entropy: fixed-point atomic + last-block ticket (deterministic, resets itself)
    if (tid == 0) {
        float part = 0.0f;
        for (int i = 0; i < RK1 * 3; i++) part += entkb[i];
        unsigned long long q =
            (unsigned long long)__double2ll_rn((double)part * 2199023255552.0); // 2^41
        atomicAdd(&g_entacc, q);
        __threadfence();
        unsigned int old = atomicAdd(&g_entticket, 1u);
        if (old == gridDim.x - 1) {
            unsigned long long tot = atomicExch(&g_entacc, 0ull);
            atomicExch(&g_entticket, 0u);
            if (out_size >= B * 24 + 1)
                out[(size_t)B * 24] =
                    (float)((double)tot * (1.0 / 2199023255552.0) / (3.0 * (double)B));
        }
    }
}

// ---------------- k2: one sample per thread; fixed-point combine ----------------
__global__ void __launch_bounds__(256) k2(const float* __restrict__ W,
                                          float* __restrict__ out, int B)
{
    __shared__ float dist_s[RK2][20];
    __shared__ float W2s[18 * 8];
    __shared__ int lastflag;

    int tid = threadIdx.x;
    int b0  = blockIdx.x * RK2;

    if (tid < 18 * NA) W2s[(tid / 6) * 8 + (tid % 6)] = W[DD * NA + tid];
    for (int i = tid; i < RK2 * 18; i += 256) {
        int r = i / 18, j = i % 18, b = b0 + r;
        if (b < B) dist_s[r][j] = g_dist[((size_t)(j / 6) * B + b) * NA + (j % 6)];
    }
    __syncthreads();

    int rl = tid >> 4;          // row within block (0..15), one per half-warp
    int sl = tid & 15;          // sample lane
    int b  = b0 + rl;
    int s  = blockIdx.y * SCHUNK + sl;
    bool act = (b < B);
    unsigned int mask = __ballot_sync(0xffffffffu, act);

    if (act) {
        float base[NA], einv[18];
#pragma unroll
        for (int a = 0; a < NA; a++) base[a] = g_base[b * NA + a];
#pragma unroll
        for (int k = 0; k < 3; k++)
#pragma unroll
            for (int a = 0; a < NA; a++)
                einv[k * 6 + a] = g_einv[((size_t)k * B + b) * NA + a];

        float p1 = 1.0f, l[NA];
#pragma unroll
        for (int a = 0; a < NA; a++) l[a] = base[a];
#pragma unroll
        for (int k = 0; k < 3; k++) {
            uint32_t c0 = (uint32_t)(((k * NS + s) * B + b) * NA);
            uint32_t mp = 0xFFFFFFFFu;
#pragma unroll
            for (int a = 0; a < NA; a++) {      // 6 independent hash chains
                float t = bits_to_t_fast(tf_fold(c0 + (uint32_t)a));
                float v = t * einv[k * 6 + a];
                uint32_t pv = (__float_as_uint(v) & 0xFFFFFFF8u) | (uint32_t)a;
                mp = (mp < pv) ? mp : pv;       // umin keeps first index on ties
            }
            int amin = (int)(mp & 7u);
            p1 *= dist_s[rl][k * 6 + amin];
#pragma unroll
            for (int a = 0; a < NA; a++) l[a] += W2s[(k * 6 + amin) * 8 + a];
        }
        float m = l[0];
#pragma unroll
        for (int a = 1; a < NA; a++) m = fmaxf(m, l[a]);
        float e[NA], S = 0.0f;
#pragma unroll
        for (int a = 0; a < NA; a++) { e[a] = __expf(l[a] - m); S += e[a]; }
        float w = p1 / S;
        float num[NA];
#pragma unroll
        for (int a = 0; a < NA; a++) num[a] = w * e[a];
        float den = p1;

#pragma unroll
        for (int off = 8; off; off >>= 1) {
#pragma unroll
            for (int a = 0; a < NA; a++)
                num[a] += __shfl_down_sync(mask, num[a], off, 16);
            den += __shfl_down_sync(mask, den, off, 16);
        }
        if (sl == 0) {
#pragma unroll
            for (int a = 0; a < NA; a++)
                atomicAdd(&g_acc[b][a],
                          (unsigned long long)__double2ll_rn((double)num[a] * FPSCALE));
            atomicAdd(&g_acc[b][6],
                      (unsigned long long)__double2ll_rn((double)den * FPSCALE));
            __threadfence();
        }
    }
    __syncthreads();

    if (tid == 0) {
        unsigned int old = atomicAdd(&g_tick[blockIdx.x], 1u);
        lastflag = (old == gridDim.y - 1) ? 1 : 0;
    }
    __syncthreads();

    if (lastflag) {
        __threadfence();
        if (tid < RK2) {
            int bb = b0 + tid;
            if (bb < B) {
                unsigned long long q[7];
#pragma unroll
                for (int i = 0; i < 7; i++) q[i] = atomicExch(&g_acc[bb][i], 0ull);
                double dden = (double)(long long)q[6];
#pragma unroll
                for (int a = 0; a < NA; a++)
                    out[(size_t)bb * NA + a] = (float)((double)(long long)q[a] / dden);
            }
        }
        if (tid == 0) atomicExch(&g_tick[blockIdx.x], 0u);
    }
}

// ---------------- launch ----------------
extern "C" void kernel_launch(void* const* d_in, const int* in_sizes, int n_in,
                              void* d_out, int out_size)
{
    const float* x    = (const float*)d_in[0];
    const float* Wopp = (const float*)d_in[1];
    const float* bopp = (const float*)d_in[2];
    const float* W    = (const float*)d_in[3];
    const float* bias = (const float*)d_in[4];
    float* out = (float*)d_out;

    int D = in_sizes[1] / (NOPP * NA);   // 512
    int B = in_sizes[0] / D;             // 4096
    if (B > 4096) B = 4096;

    k1<<<(B + RK1 - 1) / RK1, 256>>>(x, Wopp, bopp, W, bias, out, B, out_size);
    dim3 g2((B + RK2 - 1) / RK2, NS / SCHUNK);
    k2<<<g2, 256>>>(W, out, B);
}

// round 6
// speedup vs baseline: 1.1718x; 1.1718x over previous
#include <cuda_runtime.h>
#include <stdint.h>

#define NOPP 3
#define NS   80
#define NA   6
#define DD   512
#define ROWS 16    // batch rows per block
#define HROWS 8    // rows staged per pass (halves the xs buffer)

// entropy accumulator: fixed-point 2^41, reset by the last block each launch
__device__ unsigned long long g_entacc;
__device__ unsigned int g_ticket;

// ---------------- threefry2x32, key=(0,42), counter=(0,i); out = x0^x1 ----------------
__device__ __forceinline__ uint32_t tf_fold(uint32_t c1)
{
    const uint32_t KS1 = 42u;
    const uint32_t KS2 = 0x1BD11BDAu ^ 42u;   // ks0 = 0
    uint32_t x0 = 0u, x1 = c1 + KS1;
#define TFR(r) { x0 += x1; x1 = __funnelshift_l(x1, x1, (r)); x1 ^= x0; }
    TFR(13) TFR(15) TFR(26) TFR(6)
    x0 += KS1; x1 += KS2 + 1u;
    TFR(17) TFR(29) TFR(16) TFR(24)
    x0 += KS2; x1 += 2u;
    TFR(13) TFR(15) TFR(26) TFR(6)
    x1 += KS1 + 3u;
    TFR(17) TFR(29) TFR(16) TFR(24)
    x0 += KS1; x1 += KS2 + 4u;
    TFR(13) TFR(15) TFR(26) TFR(6)
    x0 += KS2; x1 += 5u;
#undef TFR
    return x0 ^ x1;
}

// t = -log(u); fast log feeds only the (monotone) argmin comparison
__device__ __forceinline__ float bits_to_t_fast(uint32_t bits)
{
    float f = __uint_as_float((bits >> 9) | 0x3f800000u) - 1.0f;
    return -__logf(f + 1.17549435e-38f);
}

__global__ void __launch_bounds__(256) kfused(
    const float* __restrict__ x, const float* __restrict__ Wopp,
    const float* __restrict__ bopp, const float* __restrict__ W,
    const float* __restrict__ bias, float* __restrict__ out,
    int B, int out_size)
{
    __shared__ float xs[HROWS * DD];         // 16 KB (two staging passes)
    __shared__ float vals[ROWS][25];
    __shared__ float einv_s[ROWS][20];
    __shared__ float dist_s[ROWS][20];
    __shared__ float base_s[ROWS][8];
    __shared__ float W2s[18 * 8];            // padded pitch 8
    __shared__ float entkb[ROWS * 3];

    int tid  = threadIdx.x;
    int warp = tid >> 5;
    int lane = tid & 31;
    int b0   = blockIdx.x * ROWS;

    // W tail (rows 512..529) into shared, padded
    if (tid < 18 * NA) W2s[(tid / 6) * 8 + (tid % 6)] = W[DD * NA + tid];

    // ---- per-warp weight columns 3w..3w+2 in registers ----
    float w0[16], w1[16], w2[16];
    {
        int c = 3 * warp;
        const float* s0 = (c + 0 < 18) ? (Wopp + (size_t)((c + 0) / 6) * DD * NA + ((c + 0) % 6))
                                       : (W + (c + 0 - 18));
        const float* s1 = (c + 1 < 18) ? (Wopp + (size_t)((c + 1) / 6) * DD * NA + ((c + 1) % 6))
                                       : (W + (c + 1 - 18));
        const float* s2 = (c + 2 < 18) ? (Wopp + (size_t)((c + 2) / 6) * DD * NA + ((c + 2) % 6))
                                       : (W + (c + 2 - 18));
#pragma unroll
        for (int j = 0; j < 16; j++) {
            size_t idx = (size_t)(lane + 32 * j) * NA;
            w0[j] = s0[idx]; w1[j] = s1[idx]; w2[j] = s2[idx];
        }
    }

    // ---- GEMM in two staging passes of HROWS rows ----
#pragma unroll
    for (int pass = 0; pass < 2; pass++) {
        int rb = pass * HROWS;
        __syncthreads();   // xs free (pass 0: W2s done too; pass 1: prior reads done)
        if (b0 + rb + HROWS <= B) {
            const float4* x4 = reinterpret_cast<const float4*>(x + (size_t)(b0 + rb) * DD);
            float4* xs4 = reinterpret_cast<float4*>(xs);
            for (int i = tid; i < HROWS * DD / 4; i += 256) xs4[i] = x4[i];
        } else {
            for (int i = tid; i < HROWS * DD; i += 256) {
                int r = i / DD;
                xs[i] = (b0 + rb + r < B) ? x[(size_t)(b0 + rb + r) * DD + (i % DD)] : 0.0f;
            }
        }
        __syncthreads();
        for (int r = 0; r < HROWS; r++) {
            const float* xr = xs + r * DD + lane;
            float a0 = 0.f, a1 = 0.f, a2 = 0.f;
#pragma unroll
            for (int j = 0; j < 16; j++) {
                float xv = xr[32 * j];
                a0 = fmaf(xv, w0[j], a0);
                a1 = fmaf(xv, w1[j], a1);
                a2 = fmaf(xv, w2[j], a2);
            }
#pragma unroll
            for (int off = 16; off; off >>= 1) {
                a0 += __shfl_down_sync(0xffffffffu, a0, off);
                a1 += __shfl_down_sync(0xffffffffu, a1, off);
                a2 += __shfl_down_sync(0xffffffffu, a2, off);
            }
            if (lane == 0) {
                vals[rb + r][3 * warp + 0] = a0;
                vals[rb + r][3 * warp + 1] = a1;
                vals[rb + r][3 * warp + 2] = a2;
            }
        }
    }
    __syncthreads();

    // ---- postprocess: softmax/einv/dist/entropy + agent base logits ----
    if (tid < ROWS * 3) {
        int r = tid / 3, k = tid % 3, b = b0 + r;
        if (b < B) {
            float l[NA], m = -1e30f;
#pragma unroll
            for (int a = 0; a < NA; a++) {
                l[a] = vals[r][k * 6 + a] + bopp[k * 6 + a];
                m = fmaxf(m, l[a]);
            }
            float e[NA], S = 0.0f;
#pragma unroll
            for (int a = 0; a < NA; a++) { e[a] = expf(l[a] - m); S += e[a]; }
            float logS = logf(S);
            float ent = 0.0f;
            size_t distoff = (size_t)B * NA + ((size_t)k * B + b) * NA;
#pragma unroll
            for (int a = 0; a < NA; a++) {
                float d = e[a] / S;
                dist_s[r][k * 6 + a] = d;
                einv_s[r][k * 6 + a] = expf(-l[a]);
                ent -= d * ((l[a] - m) - logS);
                if (out_size >= B * 24) out[distoff + a] = d;
            }
            entkb[tid] = ent;
        } else entkb[tid] = 0.0f;
    } else if (tid < ROWS * 3 + ROWS * 6) {
        int t2 = tid - ROWS * 3;
        int r = t2 / 6, a = t2 % 6, b = b0 + r;
        if (b < B) base_s[r][a] = vals[r][18 + a] + bias[a];
    }
    __syncthreads();

    // ---- entropy: fixed-point atomic + last-block ticket (deterministic) ----
    if (tid == 0) {
        float part = 0.0f;
        for (int i = 0; i < ROWS * 3; i++) part += entkb[i];
        unsigned long long q =
            (unsigned long long)__double2ll_rn((double)part * 2199023255552.0); // 2^41
        atomicAdd(&g_entacc, q);
        __threadfence();
        unsigned int old = atomicAdd(&g_ticket, 1u);
        if (old == gridDim.x - 1) {
            unsigned long long tot = atomicExch(&g_entacc, 0ull);
            atomicExch(&g_ticket, 0u);
            if (out_size >= B * 24 + 1)
                out[(size_t)B * 24] =
                    (float)((double)tot * (1.0 / 2199023255552.0) / (3.0 * (double)B));
        }
    }

    // ---- sampling: 16 lanes per batch row, 2 rows per warp, 5 samples/lane ----
    int h  = lane >> 4;
    int sl = lane & 15;
    int rl = warp * 2 + h;
    int b  = b0 + rl;
    unsigned int smask = __ballot_sync(0xffffffffu, b < B);
    if (b >= B) return;

    float base[NA], einv[18];
#pragma unroll
    for (int a = 0; a < NA; a++) base[a] = base_s[rl][a];
#pragma unroll
    for (int i = 0; i < 18; i++) einv[i] = einv_s[rl][i];

    float num[NA] = {0, 0, 0, 0, 0, 0}, den = 0.0f;

    for (int s = sl; s < NS; s += 16) {
        float p1 = 1.0f, l[NA];
#pragma unroll
        for (int a = 0; a < NA; a++) l[a] = base[a];
#pragma unroll
        for (int k = 0; k < 3; k++) {
            uint32_t c0 = (uint32_t)(((k * NS + s) * B + b) * NA);
            uint32_t mp = 0xFFFFFFFFu;
#pragma unroll
            for (int a = 0; a < NA; a++) {      // 6 independent hash chains -> ILP
                float t = bits_to_t_fast(tf_fold(c0 + (uint32_t)a));
                float v = t * einv[k * 6 + a];
                uint32_t pv = (__float_as_uint(v) & 0xFFFFFFF8u) | (uint32_t)a;
                mp = (mp < pv) ? mp : pv;       // umin keeps first index on ties
            }
            int amin = (int)(mp & 7u);
            p1 *= dist_s[rl][k * 6 + amin];
#pragma unroll
            for (int a = 0; a < NA; a++) l[a] += W2s[(k * 6 + amin) * 8 + a];
        }
        float m = l[0];
#pragma unroll
        for (int a = 1; a < NA; a++) m = fmaxf(m, l[a]);
        float e[NA], S = 0.0f;
#pragma unroll
        for (int a = 0; a < NA; a++) { e[a] = __expf(l[a] - m); S += e[a]; }
        float w = p1 / S;
#pragma unroll
        for (int a = 0; a < NA; a++) num[a] = fmaf(w, e[a], num[a]);
        den += p1;
    }
#pragma unroll
    for (int off = 8; off; off >>= 1) {
#pragma unroll
        for (int a = 0; a < NA; a++)
            num[a] += __shfl_down_sync(smask, num[a], off, 16);
        den += __shfl_down_sync(smask, den, off, 16);
    }
    if (sl == 0) {
        float inv = 1.0f / den;
#pragma unroll
        for (int a = 0; a < NA; a++) out[(size_t)b * NA + a] = num[a] * inv;
    }
}

// ---------------- launch ----------------
extern "C" void kernel_launch(void* const* d_in, const int* in_sizes, int n_in,
                              void* d_out, int out_size)
{
    const float* x    = (const float*)d_in[0];
    const float* Wopp = (const float*)d_in[1];
    const float* bopp = (const float*)d_in[2];
    const float* W    = (const float*)d_in[3];
    const float* bias = (const float*)d_in[4];
    float* out = (float*)d_out;

    int D = in_sizes[1] / (NOPP * NA);   // 512
    int B = in_sizes[0] / D;             // 4096

    int grid = (B + ROWS - 1) / ROWS;
    kfused<<<grid, 256>>>(x, Wopp, bopp, W, bias, out, B, out_size);
}